// round 15
// baseline (speedup 1.0000x reference)
#include <cuda_runtime.h>
#include <cuda_bf16.h>
#include <cuda_fp16.h>
#include <cstdint>

#define B_    4
#define N_    4096
#define K_    16
#define CIN   128
#define H     256
#define COUT  128
#define NODES (B_*N_)

__device__ __align__(16) uint16_t g_Ah[NODES*H];  // fp16: feats@W1[:128,:] + b1
__device__ __align__(16) uint16_t g_Bh[NODES*H];  // fp16: feats@W1[128:,:]
__device__ float g_S [NODES*H];                   // fp32: sum_k mask*h2
// W1 packed fp16: [hf:2][n:256][k:136]
__device__ __align__(16) uint16_t g_W1h[2*256*136];
// W2 packed fp16 (FULL, n-major): [n:256][k:264]
__device__ __align__(16) uint16_t g_W2f[256*264];
// W3 packed fp16: [n:128][k:264]
__device__ __align__(16) uint16_t g_W3h[128*264];

// ---------------- helpers ----------------
__device__ __forceinline__ uint32_t smem_u32(const void* p) {
    uint32_t a;
    asm("{ .reg .u64 t; cvta.to.shared.u64 t, %1; cvt.u32.u64 %0, t; }" : "=r"(a) : "l"(p));
    return a;
}
__device__ __forceinline__ void mma_f16(float* d, const uint32_t* a, const uint32_t* b) {
    asm volatile("mma.sync.aligned.m16n8k16.row.col.f32.f16.f16.f32 "
        "{%0,%1,%2,%3}, {%4,%5,%6,%7}, {%8,%9}, {%0,%1,%2,%3};"
        : "+f"(d[0]), "+f"(d[1]), "+f"(d[2]), "+f"(d[3])
        : "r"(a[0]), "r"(a[1]), "r"(a[2]), "r"(a[3]), "r"(b[0]), "r"(b[1]));
}
__device__ __forceinline__ void cp16(uint32_t sdst, const void* gsrc) {
    asm volatile("cp.async.cg.shared.global [%0], [%1], 16;" :: "r"(sdst), "l"(gsrc));
}
__device__ __forceinline__ uint32_t pack_h2(float x, float y) {
    __half2 p = __floats2half2_rn(x, y);
    return *reinterpret_cast<uint32_t*>(&p);
}
__device__ __forceinline__ uint32_t relu_add_h2(uint32_t a, uint32_t b) {
    __half2 ha = *reinterpret_cast<__half2*>(&a);
    __half2 hb = *reinterpret_cast<__half2*>(&b);
    __half2 z  = __floats2half2_rn(0.f, 0.f);
    __half2 r  = __hmax2(__hadd2(ha, hb), z);
    return *reinterpret_cast<uint32_t*>(&r);
}

// ---------------------------------------------------------------------------
// k0: pack W2 (fp16 full n-major), W1 (fp16), W3 (fp16 n-major). Bounds-clean.
// ---------------------------------------------------------------------------
__global__ void k0_prep(const float* __restrict__ W1, const float* __restrict__ W2,
                        const float* __restrict__ W3)
{
    int i = blockIdx.x * 256 + threadIdx.x;
    if (i < 67584) {                                   // W2: [n:256][k:264]
        int k = i % 264, n = i / 264;
        __half v = (k < 256) ? __float2half_rn(W2[k*256 + n]) : __half(0.f);
        g_W2f[i] = *reinterpret_cast<uint16_t*>(&v);
    } else if (i < 67584 + 69632) {                    // W1: [hf][n][136] fp16
        int j = i - 67584;
        int k = j % 136, n = (j / 136) % 256, hf = j / 34816;
        __half v = (k < 128) ? __float2half_rn(W1[(hf*128 + k)*256 + n]) : __half(0.f);
        g_W1h[j] = *reinterpret_cast<uint16_t*>(&v);
    } else if (i < 67584 + 69632 + 33792) {            // W3: [n:128][k:264] fp16
        int j = i - 137216;
        int k = j % 264, n = j / 264;
        __half v = (k < 256) ? __float2half_rn(W3[k*COUT + n]) : __half(0.f);
        g_W3h[j] = *reinterpret_cast<uint16_t*>(&v);
    }
}

// ---------------------------------------------------------------------------
// k1 (HMMA fp16 single-term, R12-proven): grid (128, 2)
// ---------------------------------------------------------------------------
#define OFF1_W  0          // fp16 [256][136] = 69632 B
#define OFF1_A  69632      // fp16 [128][136] = 34816 B
#define OFF1_B1 104448     // 256 floats
#define SMEM1   105472

__global__ __launch_bounds__(256, 1)
void k1_hmma(const float* __restrict__ feats, const float* __restrict__ b1)
{
    extern __shared__ char sm1[];
    uint16_t* sW  = (uint16_t*)(sm1 + OFF1_W);
    uint16_t* sA  = (uint16_t*)(sm1 + OFF1_A);
    float*    sb1 = (float*)(sm1 + OFF1_B1);
    uint32_t  swb = smem_u32(sm1);

    int tid = threadIdx.x, lane = tid & 31, wid = tid >> 5;
    int wm = wid >> 2, wn = wid & 3, g4 = lane >> 2, l4 = lane & 3;
    int m0 = blockIdx.x * 128, hf = blockIdx.y;

    {
        const char* src = (const char*)(g_W1h + hf*34816) + tid*16;
        uint32_t dst = swb + OFF1_W + tid*16;
        #pragma unroll
        for (int it = 0; it < 17; ++it) cp16(dst + it*4096, src + it*4096);
        asm volatile("cp.async.commit_group;" ::: "memory");
    }
    sb1[tid] = (hf == 0) ? b1[tid] : 0.f;

    {
        int r = tid >> 1, kb = (tid & 1) * 64;
        const float* fr = feats + (size_t)(m0 + r)*CIN + kb;
        uint16_t* ph = sA + r*136 + kb;
        #pragma unroll
        for (int j = 0; j < 16; ++j) {
            float4 v = *(const float4*)(fr + 4*j);
            *(uint32_t*)(ph + 4*j)     = pack_h2(v.x, v.y);
            *(uint32_t*)(ph + 4*j + 2) = pack_h2(v.z, v.w);
        }
    }
    asm volatile("cp.async.wait_group 0;" ::: "memory");
    __syncthreads();

    float acc[4][8][4];
    #pragma unroll
    for (int mi = 0; mi < 4; ++mi)
        #pragma unroll
        for (int ni = 0; ni < 8; ++ni)
            #pragma unroll
            for (int q = 0; q < 4; ++q) acc[mi][ni][q] = 0.f;

    #pragma unroll
    for (int ks = 0; ks < 8; ++ks) {
        int kk = ks*16 + l4*2;
        uint32_t ah[4][4], bb[8][2];
        #pragma unroll
        for (int mi = 0; mi < 4; ++mi) {
            const uint16_t* pa = sA + (wm*64 + mi*16 + g4)*136 + kk;
            ah[mi][0] = *(const uint32_t*)pa;
            ah[mi][1] = *(const uint32_t*)(pa + 8*136);
            ah[mi][2] = *(const uint32_t*)(pa + 8);
            ah[mi][3] = *(const uint32_t*)(pa + 8*136 + 8);
        }
        #pragma unroll
        for (int ni = 0; ni < 8; ++ni) {
            const uint16_t* p = sW + (wn*64 + ni*8 + g4)*136 + kk;
            bb[ni][0] = *(const uint32_t*)p;
            bb[ni][1] = *(const uint32_t*)(p + 8);
        }
        #pragma unroll
        for (int mi = 0; mi < 4; ++mi)
            #pragma unroll
            for (int ni = 0; ni < 8; ++ni)
                mma_f16(acc[mi][ni], ah[mi], bb[ni]);
    }

    uint16_t* Out = hf ? g_Bh : g_Ah;
    #pragma unroll
    for (int mi = 0; mi < 4; ++mi) {
        int m = wm*64 + mi*16 + g4;
        #pragma unroll
        for (int ni = 0; ni < 8; ++ni) {
            int n0 = wn*64 + ni*8 + l4*2;
            float b0 = sb1[n0], bv1 = sb1[n0 + 1];
            *(uint32_t*)(Out + (size_t)(m0 + m)*H + n0) =
                pack_h2(acc[mi][ni][0] + b0, acc[mi][ni][1] + bv1);
            *(uint32_t*)(Out + (size_t)(m0 + m + 8)*H + n0) =
                pack_h2(acc[mi][ni][2] + b0, acc[mi][ni][3] + bv1);
        }
    }
}

// ---------------------------------------------------------------------------
// k2: edge MLP layer-2, fp16 HMMA, W2 resident, SPLIT-STREAM (k-halves) so
// mma on k 0..127 overlaps the second half's arrival.
// ---------------------------------------------------------------------------
#define OFF_H1   0          // fp16 [128][264] = 67584
#define OFF_W2   67584      // fp16 [256][264] = 135168 -> 202752
#define OFF_B2   202752
#define OFF_SIDX 203776
#define OFF_SVAL 204288
#define SMEM2    204800

__global__ __launch_bounds__(256, 1)
void k2_edge(const int* __restrict__ n_idxs, const int* __restrict__ nvalid,
             const float* __restrict__ b2)
{
    extern __shared__ char smem[];
    uint16_t* sh1  = (uint16_t*)(smem + OFF_H1);
    uint16_t* sW2  = (uint16_t*)(smem + OFF_W2);
    float*    sb2  = (float*)(smem + OFF_B2);
    int*      sidx = (int*)(smem + OFF_SIDX);
    float*    sval = (float*)(smem + OFF_SVAL);
    uint32_t  swb  = smem_u32(smem) + OFF_W2;

    int tid = threadIdx.x, lane = tid & 31, wid = tid >> 5;
    int wm = wid >> 2, wn = wid & 3;
    int node0 = blockIdx.x * 8;

    // group0: W2 k[0,128) -- 256 rows x 256B = 65536B, 16 pieces/row
    #pragma unroll
    for (int it = 0; it < 16; ++it) {
        int i = tid + 256*it;
        int row = i >> 4, piece = i & 15;
        cp16(swb + row*528 + piece*16, g_W2f + row*264 + piece*8);
    }
    asm volatile("cp.async.commit_group;" ::: "memory");
    // group1: W2 k[128,264) -- 256 rows x 272B, 17 pieces/row (4352 = 17x256)
    #pragma unroll
    for (int it = 0; it < 17; ++it) {
        int i = tid + 256*it;
        int row = i / 17, piece = i % 17;
        cp16(swb + row*528 + 256 + piece*16, g_W2f + row*264 + 128 + piece*8);
    }
    asm volatile("cp.async.commit_group;" ::: "memory");

    if (tid < 128) {
        sidx[tid] = n_idxs[node0*K_ + tid];
        sval[tid] = nvalid[node0*K_ + tid] ? 1.f : 0.f;
    }
    sb2[tid] = b2[tid];
    __syncthreads();   // sidx visible

    // build h1 (fp16): warp w owns node node0+w; 16 edges, 1 LDG.128/edge.
    {
        int node = node0 + wid;
        int boff = (node >> 12) * N_;
        const uint16_t* arow = g_Ah + (size_t)node * H;
        uint4 a = *(const uint4*)(arow + 8*lane);
        #pragma unroll 4
        for (int i = 0; i < 16; ++i) {
            int e = wid*16 + i;
            const uint16_t* brow = g_Bh + (size_t)(boff + sidx[e]) * H;
            uint4 v = *(const uint4*)(brow + 8*lane);
            uint4 h;
            h.x = relu_add_h2(a.x, v.x);
            h.y = relu_add_h2(a.y, v.y);
            h.z = relu_add_h2(a.z, v.z);
            h.w = relu_add_h2(a.w, v.w);
            *(uint4*)(sh1 + e*264 + 8*lane) = h;
        }
    }

    float acc[4][8][4];
    #pragma unroll
    for (int mi = 0; mi < 4; ++mi)
        #pragma unroll
        for (int ni = 0; ni < 8; ++ni)
            #pragma unroll
            for (int q = 0; q < 4; ++q) acc[mi][ni][q] = 0.f;

    int g4 = lane >> 2, l4 = lane & 3;

    // first half of W2 ready -> mma k-steps 0..7
    asm volatile("cp.async.wait_group 1;" ::: "memory");
    __syncthreads();
    #pragma unroll
    for (int ks = 0; ks < 8; ++ks) {
        int kk = ks*16 + l4*2;
        uint32_t ah[4][4], bb[8][2];
        #pragma unroll
        for (int mi = 0; mi < 4; ++mi) {
            const uint16_t* pa = sh1 + (wm*64 + mi*16 + g4)*264 + kk;
            ah[mi][0] = *(const uint32_t*)pa;
            ah[mi][1] = *(const uint32_t*)(pa + 8*264);
            ah[mi][2] = *(const uint32_t*)(pa + 8);
            ah[mi][3] = *(const uint32_t*)(pa + 8*264 + 8);
        }
        #pragma unroll
        for (int ni = 0; ni < 8; ++ni) {
            const uint16_t* p = sW2 + (wn*64 + ni*8 + g4)*264 + kk;
            bb[ni][0] = *(const uint32_t*)p;
            bb[ni][1] = *(const uint32_t*)(p + 8);
        }
        #pragma unroll
        for (int mi = 0; mi < 4; ++mi)
            #pragma unroll
            for (int ni = 0; ni < 8; ++ni)
                mma_f16(acc[mi][ni], ah[mi], bb[ni]);
    }
    // second half ready -> mma k-steps 8..15
    asm volatile("cp.async.wait_group 0;" ::: "memory");
    __syncthreads();
    #pragma unroll
    for (int ks = 8; ks < 16; ++ks) {
        int kk = ks*16 + l4*2;
        uint32_t ah[4][4], bb[8][2];
        #pragma unroll
        for (int mi = 0; mi < 4; ++mi) {
            const uint16_t* pa = sh1 + (wm*64 + mi*16 + g4)*264 + kk;
            ah[mi][0] = *(const uint32_t*)pa;
            ah[mi][1] = *(const uint32_t*)(pa + 8*264);
            ah[mi][2] = *(const uint32_t*)(pa + 8);
            ah[mi][3] = *(const uint32_t*)(pa + 8*264 + 8);
        }
        #pragma unroll
        for (int ni = 0; ni < 8; ++ni) {
            const uint16_t* p = sW2 + (wn*64 + ni*8 + g4)*264 + kk;
            bb[ni][0] = *(const uint32_t*)p;
            bb[ni][1] = *(const uint32_t*)(p + 8);
        }
        #pragma unroll
        for (int mi = 0; mi < 4; ++mi)
            #pragma unroll
            for (int ni = 0; ni < 8; ++ni)
                mma_f16(acc[mi][ni], ah[mi], bb[ni]);
    }

    // epilogue: bias + relu + mask, butterfly over 16 edges, store g_S
    #pragma unroll
    for (int mi = 0; mi < 4; ++mi) {
        int node_l = wm*4 + mi;
        float m1 = sval[node_l*16 + g4];
        float m2 = sval[node_l*16 + g4 + 8];
        int node_g = node0 + node_l;
        #pragma unroll
        for (int ni = 0; ni < 8; ++ni) {
            int n0 = wn*64 + ni*8 + l4*2;
            float s0 = fmaxf(acc[mi][ni][0] + sb2[n0],     0.f)*m1
                     + fmaxf(acc[mi][ni][2] + sb2[n0],     0.f)*m2;
            float s1 = fmaxf(acc[mi][ni][1] + sb2[n0 + 1], 0.f)*m1
                     + fmaxf(acc[mi][ni][3] + sb2[n0 + 1], 0.f)*m2;
            #pragma unroll
            for (int d = 4; d < 32; d <<= 1) {
                s0 += __shfl_xor_sync(0xFFFFFFFF, s0, d);
                s1 += __shfl_xor_sync(0xFFFFFFFF, s1, d);
            }
            if (g4 == 0)
                *(float2*)(g_S + (size_t)node_g*H + n0) = make_float2(s0, s1);
        }
    }
}

// ---------------------------------------------------------------------------
// k3 (fp16 single-term, BM=64, grid 256, 2 CTAs/SM): out = S @ W3 + b3*cnt
// ---------------------------------------------------------------------------
#define G3_A   0          // fp16 [64][264] = 33792
#define G3_W   33792      // fp16 [128][264] = 67584 -> 101376
#define G3_B3  101376     // 128 f -> 101888
#define G3_CNT 101888     // 64 f -> 102144
#define SMEM3  102400

__global__ __launch_bounds__(256, 2)
void k3_hmma(const int* __restrict__ nvalid, const float* __restrict__ b3,
             float* __restrict__ out)
{
    extern __shared__ char sm3[];
    uint16_t* sA   = (uint16_t*)(sm3 + G3_A);
    uint16_t* sW3  = (uint16_t*)(sm3 + G3_W);
    float*    sb3  = (float*)(sm3 + G3_B3);
    float*    scnt = (float*)(sm3 + G3_CNT);
    uint32_t  swb  = smem_u32(sm3);

    int tid = threadIdx.x, lane = tid & 31, wid = tid >> 5;
    int wm = wid >> 2, wn = wid & 3, g4 = lane >> 2, l4 = lane & 3;
    int m0 = blockIdx.x * 64;

    // stream W3 (67584B): 17 iters, guarded
    {
        const char* src = (const char*)g_W3h + tid*16;
        uint32_t dst = swb + G3_W + tid*16;
        #pragma unroll
        for (int it = 0; it < 17; ++it)
            if (it*4096 + tid*16 < 67584) cp16(dst + it*4096, src + it*4096);
        asm volatile("cp.async.commit_group;" ::: "memory");
    }
    if (tid < 128) sb3[tid] = b3[tid];
    if (tid < 64) {
        int c = 0;
        #pragma unroll
        for (int k = 0; k < K_; ++k) c += nvalid[(m0 + tid)*K_ + k];
        scnt[tid] = (float)c;
    }

    // build A (fp16): thread -> row tid/4, k-quarter (tid&3)*64
    {
        int r = tid >> 2, kb = (tid & 3) * 64;
        const float* fr = g_S + (size_t)(m0 + r)*H + kb;
        uint16_t* ph = sA + r*264 + kb;
        #pragma unroll
        for (int j = 0; j < 16; ++j) {
            float4 v = *(const float4*)(fr + 4*j);
            *(uint32_t*)(ph + 4*j)     = pack_h2(v.x, v.y);
            *(uint32_t*)(ph + 4*j + 2) = pack_h2(v.z, v.w);
        }
    }
    asm volatile("cp.async.wait_group 0;" ::: "memory");
    __syncthreads();

    float acc[2][4][4];
    #pragma unroll
    for (int mi = 0; mi < 2; ++mi)
        #pragma unroll
        for (int ni = 0; ni < 4; ++ni)
            #pragma unroll
            for (int q = 0; q < 4; ++q) acc[mi][ni][q] = 0.f;

    #pragma unroll
    for (int ks = 0; ks < 16; ++ks) {
        int kk = ks*16 + l4*2;
        uint32_t ah[2][4], bb[4][2];
        #pragma unroll
        for (int mi = 0; mi < 2; ++mi) {
            const uint16_t* pa = sA + (wm*32 + mi*16 + g4)*264 + kk;
            ah[mi][0] = *(const uint32_t*)pa;
            ah[mi][1] = *(const uint32_t*)(pa + 8*264);
            ah[mi][2] = *(const uint32_t*)(pa + 8);
            ah[mi][3] = *(const uint32_t*)(pa + 8*264 + 8);
        }
        #pragma unroll
        for (int ni = 0; ni < 4; ++ni) {
            const uint16_t* p = sW3 + (wn*32 + ni*8 + g4)*264 + kk;
            bb[ni][0] = *(const uint32_t*)p;
            bb[ni][1] = *(const uint32_t*)(p + 8);
        }
        #pragma unroll
        for (int mi = 0; mi < 2; ++mi)
            #pragma unroll
            for (int ni = 0; ni < 4; ++ni)
                mma_f16(acc[mi][ni], ah[mi], bb[ni]);
    }

    #pragma unroll
    for (int mi = 0; mi < 2; ++mi) {
        int m = wm*32 + mi*16 + g4;
        float c0 = scnt[m], c1 = scnt[m + 8];
        #pragma unroll
        for (int ni = 0; ni < 4; ++ni) {
            int n0 = wn*32 + ni*8 + l4*2;
            float b0 = sb3[n0], bv1 = sb3[n0 + 1];
            *(float2*)(out + (size_t)(m0 + m)*COUT + n0) =
                make_float2(acc[mi][ni][0] + b0*c0, acc[mi][ni][1] + bv1*c0);
            *(float2*)(out + (size_t)(m0 + m + 8)*COUT + n0) =
                make_float2(acc[mi][ni][2] + b0*c1, acc[mi][ni][3] + bv1*c1);
        }
    }
}

// ---------------------------------------------------------------------------
extern "C" void kernel_launch(void* const* d_in, const int* in_sizes, int n_in,
                              void* d_out, int out_size)
{
    const float* feats  = (const float*)d_in[2];
    const int*   n_idxs = (const int*)  d_in[3];
    const int*   nvalid = (const int*)  d_in[4];
    const float* W1     = (const float*)d_in[5];
    const float* b1     = (const float*)d_in[6];
    const float* W2     = (const float*)d_in[7];
    const float* b2     = (const float*)d_in[8];
    const float* W3     = (const float*)d_in[9];
    const float* b3     = (const float*)d_in[10];
    float* out = (float*)d_out;

    cudaFuncSetAttribute(k1_hmma, cudaFuncAttributeMaxDynamicSharedMemorySize, SMEM1);
    cudaFuncSetAttribute(k2_edge, cudaFuncAttributeMaxDynamicSharedMemorySize, SMEM2);
    cudaFuncSetAttribute(k3_hmma, cudaFuncAttributeMaxDynamicSharedMemorySize, SMEM3);

    k0_prep<<<668, 256>>>(W1, W2, W3);
    k1_hmma<<<dim3(128, 2), 256, SMEM1>>>(feats, b1);
    k2_edge<<<NODES/8, 256, SMEM2>>>(n_idxs, nvalid, b2);
    k3_hmma<<<256, 256, SMEM3>>>(nvalid, b3, out);
}

// round 16
// speedup vs baseline: 1.0553x; 1.0553x over previous
#include <cuda_runtime.h>
#include <cuda_bf16.h>
#include <cuda_fp16.h>
#include <cstdint>

#define B_    4
#define N_    4096
#define K_    16
#define CIN   128
#define H     256
#define COUT  128
#define NODES (B_*N_)

__device__ __align__(16) uint16_t g_Ah[NODES*H];  // fp16: feats@W1[:128,:] + b1
__device__ __align__(16) uint16_t g_Bh[NODES*H];  // fp16: feats@W1[128:,:]
__device__ float g_S [NODES*H];                   // fp32: sum_k mask*h2
// W1 packed fp16: [hf:2][n:256][k:136]
__device__ __align__(16) uint16_t g_W1h[2*256*136];
// W2 packed fp16 (FULL, n-major): [n:256][k:264]
__device__ __align__(16) uint16_t g_W2f[256*264];
// W3 packed fp16: [n:128][k:264]
__device__ __align__(16) uint16_t g_W3h[128*264];

// ---------------- helpers ----------------
__device__ __forceinline__ uint32_t smem_u32(const void* p) {
    uint32_t a;
    asm("{ .reg .u64 t; cvta.to.shared.u64 t, %1; cvt.u32.u64 %0, t; }" : "=r"(a) : "l"(p));
    return a;
}
__device__ __forceinline__ void mma_f16(float* d, const uint32_t* a, const uint32_t* b) {
    asm volatile("mma.sync.aligned.m16n8k16.row.col.f32.f16.f16.f32 "
        "{%0,%1,%2,%3}, {%4,%5,%6,%7}, {%8,%9}, {%0,%1,%2,%3};"
        : "+f"(d[0]), "+f"(d[1]), "+f"(d[2]), "+f"(d[3])
        : "r"(a[0]), "r"(a[1]), "r"(a[2]), "r"(a[3]), "r"(b[0]), "r"(b[1]));
}
__device__ __forceinline__ void cp16(uint32_t sdst, const void* gsrc) {
    asm volatile("cp.async.cg.shared.global [%0], [%1], 16;" :: "r"(sdst), "l"(gsrc));
}
__device__ __forceinline__ uint32_t pack_h2(float x, float y) {
    __half2 p = __floats2half2_rn(x, y);
    return *reinterpret_cast<uint32_t*>(&p);
}
__device__ __forceinline__ uint32_t relu_add_h2(uint32_t a, uint32_t b) {
    __half2 ha = *reinterpret_cast<__half2*>(&a);
    __half2 hb = *reinterpret_cast<__half2*>(&b);
    __half2 z  = __floats2half2_rn(0.f, 0.f);
    __half2 r  = __hmax2(__hadd2(ha, hb), z);
    return *reinterpret_cast<uint32_t*>(&r);
}

// ---------------------------------------------------------------------------
// k0: pack W2 (fp16 full n-major), W1 (fp16), W3 (fp16 n-major). Bounds-clean.
// ---------------------------------------------------------------------------
__global__ void k0_prep(const float* __restrict__ W1, const float* __restrict__ W2,
                        const float* __restrict__ W3)
{
    int i = blockIdx.x * 256 + threadIdx.x;
    if (i < 67584) {                                   // W2: [n:256][k:264]
        int k = i % 264, n = i / 264;
        __half v = (k < 256) ? __float2half_rn(W2[k*256 + n]) : __half(0.f);
        g_W2f[i] = *reinterpret_cast<uint16_t*>(&v);
    } else if (i < 67584 + 69632) {                    // W1: [hf][n][136] fp16
        int j = i - 67584;
        int k = j % 136, n = (j / 136) % 256, hf = j / 34816;
        __half v = (k < 128) ? __float2half_rn(W1[(hf*128 + k)*256 + n]) : __half(0.f);
        g_W1h[j] = *reinterpret_cast<uint16_t*>(&v);
    } else if (i < 67584 + 69632 + 33792) {            // W3: [n:128][k:264] fp16
        int j = i - 137216;
        int k = j % 264, n = j / 264;
        __half v = (k < 256) ? __float2half_rn(W3[k*COUT + n]) : __half(0.f);
        g_W3h[j] = *reinterpret_cast<uint16_t*>(&v);
    }
}

// ---------------------------------------------------------------------------
// k1 (HMMA fp16 single-term, R12-proven): grid (128, 2)
// ---------------------------------------------------------------------------
#define OFF1_W  0          // fp16 [256][136] = 69632 B
#define OFF1_A  69632      // fp16 [128][136] = 34816 B
#define OFF1_B1 104448     // 256 floats
#define SMEM1   105472

__global__ __launch_bounds__(256, 1)
void k1_hmma(const float* __restrict__ feats, const float* __restrict__ b1)
{
    extern __shared__ char sm1[];
    uint16_t* sW  = (uint16_t*)(sm1 + OFF1_W);
    uint16_t* sA  = (uint16_t*)(sm1 + OFF1_A);
    float*    sb1 = (float*)(sm1 + OFF1_B1);
    uint32_t  swb = smem_u32(sm1);

    int tid = threadIdx.x, lane = tid & 31, wid = tid >> 5;
    int wm = wid >> 2, wn = wid & 3, g4 = lane >> 2, l4 = lane & 3;
    int m0 = blockIdx.x * 128, hf = blockIdx.y;

    {
        const char* src = (const char*)(g_W1h + hf*34816) + tid*16;
        uint32_t dst = swb + OFF1_W + tid*16;
        #pragma unroll
        for (int it = 0; it < 17; ++it) cp16(dst + it*4096, src + it*4096);
        asm volatile("cp.async.commit_group;" ::: "memory");
    }
    sb1[tid] = (hf == 0) ? b1[tid] : 0.f;

    {
        int r = tid >> 1, kb = (tid & 1) * 64;
        const float* fr = feats + (size_t)(m0 + r)*CIN + kb;
        uint16_t* ph = sA + r*136 + kb;
        #pragma unroll
        for (int j = 0; j < 16; ++j) {
            float4 v = *(const float4*)(fr + 4*j);
            *(uint32_t*)(ph + 4*j)     = pack_h2(v.x, v.y);
            *(uint32_t*)(ph + 4*j + 2) = pack_h2(v.z, v.w);
        }
    }
    asm volatile("cp.async.wait_group 0;" ::: "memory");
    __syncthreads();

    float acc[4][8][4];
    #pragma unroll
    for (int mi = 0; mi < 4; ++mi)
        #pragma unroll
        for (int ni = 0; ni < 8; ++ni)
            #pragma unroll
            for (int q = 0; q < 4; ++q) acc[mi][ni][q] = 0.f;

    #pragma unroll
    for (int ks = 0; ks < 8; ++ks) {
        int kk = ks*16 + l4*2;
        uint32_t ah[4][4], bb[8][2];
        #pragma unroll
        for (int mi = 0; mi < 4; ++mi) {
            const uint16_t* pa = sA + (wm*64 + mi*16 + g4)*136 + kk;
            ah[mi][0] = *(const uint32_t*)pa;
            ah[mi][1] = *(const uint32_t*)(pa + 8*136);
            ah[mi][2] = *(const uint32_t*)(pa + 8);
            ah[mi][3] = *(const uint32_t*)(pa + 8*136 + 8);
        }
        #pragma unroll
        for (int ni = 0; ni < 8; ++ni) {
            const uint16_t* p = sW + (wn*64 + ni*8 + g4)*136 + kk;
            bb[ni][0] = *(const uint32_t*)p;
            bb[ni][1] = *(const uint32_t*)(p + 8);
        }
        #pragma unroll
        for (int mi = 0; mi < 4; ++mi)
            #pragma unroll
            for (int ni = 0; ni < 8; ++ni)
                mma_f16(acc[mi][ni], ah[mi], bb[ni]);
    }

    uint16_t* Out = hf ? g_Bh : g_Ah;
    #pragma unroll
    for (int mi = 0; mi < 4; ++mi) {
        int m = wm*64 + mi*16 + g4;
        #pragma unroll
        for (int ni = 0; ni < 8; ++ni) {
            int n0 = wn*64 + ni*8 + l4*2;
            float b0 = sb1[n0], bv1 = sb1[n0 + 1];
            *(uint32_t*)(Out + (size_t)(m0 + m)*H + n0) =
                pack_h2(acc[mi][ni][0] + b0, acc[mi][ni][1] + bv1);
            *(uint32_t*)(Out + (size_t)(m0 + m + 8)*H + n0) =
                pack_h2(acc[mi][ni][2] + b0, acc[mi][ni][3] + bv1);
        }
    }
}

// ---------------------------------------------------------------------------
// k2 (R14-proven): fp16 HMMA, W2 fully resident (single 33-iter burst),
// no mainloop syncs. Coalesced warp-per-node gather.
// ---------------------------------------------------------------------------
#define OFF_H1   0          // fp16 [128][264] = 67584
#define OFF_W2   67584      // fp16 [256][264] = 135168 -> 202752
#define OFF_B2   202752
#define OFF_SIDX 203776
#define OFF_SVAL 204288
#define SMEM2    204800

__global__ __launch_bounds__(256, 1)
void k2_edge(const int* __restrict__ n_idxs, const int* __restrict__ nvalid,
             const float* __restrict__ b2)
{
    extern __shared__ char smem[];
    uint16_t* sh1  = (uint16_t*)(smem + OFF_H1);
    uint16_t* sW2  = (uint16_t*)(smem + OFF_W2);
    float*    sb2  = (float*)(smem + OFF_B2);
    int*      sidx = (int*)(smem + OFF_SIDX);
    float*    sval = (float*)(smem + OFF_SVAL);
    uint32_t  swb  = smem_u32(smem) + OFF_W2;

    int tid = threadIdx.x, lane = tid & 31, wid = tid >> 5;
    int wm = wid >> 2, wn = wid & 3;
    int node0 = blockIdx.x * 8;

    // stream FULL W2 once: 135168 B = 33 x 16B/thread
    {
        const char* src = (const char*)g_W2f + tid*16;
        uint32_t dst = swb + tid*16;
        #pragma unroll
        for (int it = 0; it < 33; ++it) cp16(dst + it*4096, src + it*4096);
        asm volatile("cp.async.commit_group;" ::: "memory");
    }

    if (tid < 128) {
        sidx[tid] = n_idxs[node0*K_ + tid];
        sval[tid] = nvalid[node0*K_ + tid] ? 1.f : 0.f;
    }
    sb2[tid] = b2[tid];
    __syncthreads();   // sidx visible

    // build h1 (fp16): warp w owns node node0+w; 16 edges, 1 LDG.128/edge.
    {
        int node = node0 + wid;
        int boff = (node >> 12) * N_;
        const uint16_t* arow = g_Ah + (size_t)node * H;
        uint4 a = *(const uint4*)(arow + 8*lane);
        #pragma unroll 4
        for (int i = 0; i < 16; ++i) {
            int e = wid*16 + i;
            const uint16_t* brow = g_Bh + (size_t)(boff + sidx[e]) * H;
            uint4 v = *(const uint4*)(brow + 8*lane);
            uint4 h;
            h.x = relu_add_h2(a.x, v.x);
            h.y = relu_add_h2(a.y, v.y);
            h.z = relu_add_h2(a.z, v.z);
            h.w = relu_add_h2(a.w, v.w);
            *(uint4*)(sh1 + e*264 + 8*lane) = h;
        }
    }
    asm volatile("cp.async.wait_group 0;" ::: "memory");
    __syncthreads();

    float acc[4][8][4];
    #pragma unroll
    for (int mi = 0; mi < 4; ++mi)
        #pragma unroll
        for (int ni = 0; ni < 8; ++ni)
            #pragma unroll
            for (int q = 0; q < 4; ++q) acc[mi][ni][q] = 0.f;

    int g4 = lane >> 2, l4 = lane & 3;

    // mainloop: 16 k-steps, NO syncs, NO waits.
    #pragma unroll 4
    for (int ks = 0; ks < 16; ++ks) {
        int kk = ks*16 + l4*2;
        uint32_t ah[4][4], bb[8][2];
        #pragma unroll
        for (int mi = 0; mi < 4; ++mi) {
            const uint16_t* pa = sh1 + (wm*64 + mi*16 + g4)*264 + kk;
            ah[mi][0] = *(const uint32_t*)pa;
            ah[mi][1] = *(const uint32_t*)(pa + 8*264);
            ah[mi][2] = *(const uint32_t*)(pa + 8);
            ah[mi][3] = *(const uint32_t*)(pa + 8*264 + 8);
        }
        #pragma unroll
        for (int ni = 0; ni < 8; ++ni) {
            const uint16_t* p = sW2 + (wn*64 + ni*8 + g4)*264 + kk;
            bb[ni][0] = *(const uint32_t*)p;
            bb[ni][1] = *(const uint32_t*)(p + 8);
        }
        #pragma unroll
        for (int mi = 0; mi < 4; ++mi)
            #pragma unroll
            for (int ni = 0; ni < 8; ++ni)
                mma_f16(acc[mi][ni], ah[mi], bb[ni]);
    }

    // epilogue: bias + relu + mask, butterfly over 16 edges, store g_S
    #pragma unroll
    for (int mi = 0; mi < 4; ++mi) {
        int node_l = wm*4 + mi;
        float m1 = sval[node_l*16 + g4];
        float m2 = sval[node_l*16 + g4 + 8];
        int node_g = node0 + node_l;
        #pragma unroll
        for (int ni = 0; ni < 8; ++ni) {
            int n0 = wn*64 + ni*8 + l4*2;
            float s0 = fmaxf(acc[mi][ni][0] + sb2[n0],     0.f)*m1
                     + fmaxf(acc[mi][ni][2] + sb2[n0],     0.f)*m2;
            float s1 = fmaxf(acc[mi][ni][1] + sb2[n0 + 1], 0.f)*m1
                     + fmaxf(acc[mi][ni][3] + sb2[n0 + 1], 0.f)*m2;
            #pragma unroll
            for (int d = 4; d < 32; d <<= 1) {
                s0 += __shfl_xor_sync(0xFFFFFFFF, s0, d);
                s1 += __shfl_xor_sync(0xFFFFFFFF, s1, d);
            }
            if (g4 == 0)
                *(float2*)(g_S + (size_t)node_g*H + n0) = make_float2(s0, s1);
        }
    }
}

// ---------------------------------------------------------------------------
// k3 (R15-proven): fp16 single-term, BM=64, grid 256, 2 CTAs/SM
// ---------------------------------------------------------------------------
#define G3_A   0          // fp16 [64][264] = 33792
#define G3_W   33792      // fp16 [128][264] = 67584 -> 101376
#define G3_B3  101376
#define G3_CNT 101888
#define SMEM3  102400

__global__ __launch_bounds__(256, 2)
void k3_hmma(const int* __restrict__ nvalid, const float* __restrict__ b3,
             float* __restrict__ out)
{
    extern __shared__ char sm3[];
    uint16_t* sA   = (uint16_t*)(sm3 + G3_A);
    uint16_t* sW3  = (uint16_t*)(sm3 + G3_W);
    float*    sb3  = (float*)(sm3 + G3_B3);
    float*    scnt = (float*)(sm3 + G3_CNT);
    uint32_t  swb  = smem_u32(sm3);

    int tid = threadIdx.x, lane = tid & 31, wid = tid >> 5;
    int wm = wid >> 2, wn = wid & 3, g4 = lane >> 2, l4 = lane & 3;
    int m0 = blockIdx.x * 64;

    {
        const char* src = (const char*)g_W3h + tid*16;
        uint32_t dst = swb + G3_W + tid*16;
        #pragma unroll
        for (int it = 0; it < 17; ++it)
            if (it*4096 + tid*16 < 67584) cp16(dst + it*4096, src + it*4096);
        asm volatile("cp.async.commit_group;" ::: "memory");
    }
    if (tid < 128) sb3[tid] = b3[tid];
    if (tid < 64) {
        int c = 0;
        #pragma unroll
        for (int k = 0; k < K_; ++k) c += nvalid[(m0 + tid)*K_ + k];
        scnt[tid] = (float)c;
    }

    {
        int r = tid >> 2, kb = (tid & 3) * 64;
        const float* fr = g_S + (size_t)(m0 + r)*H + kb;
        uint16_t* ph = sA + r*264 + kb;
        #pragma unroll
        for (int j = 0; j < 16; ++j) {
            float4 v = *(const float4*)(fr + 4*j);
            *(uint32_t*)(ph + 4*j)     = pack_h2(v.x, v.y);
            *(uint32_t*)(ph + 4*j + 2) = pack_h2(v.z, v.w);
        }
    }
    asm volatile("cp.async.wait_group 0;" ::: "memory");
    __syncthreads();

    float acc[2][4][4];
    #pragma unroll
    for (int mi = 0; mi < 2; ++mi)
        #pragma unroll
        for (int ni = 0; ni < 4; ++ni)
            #pragma unroll
            for (int q = 0; q < 4; ++q) acc[mi][ni][q] = 0.f;

    #pragma unroll
    for (int ks = 0; ks < 16; ++ks) {
        int kk = ks*16 + l4*2;
        uint32_t ah[2][4], bb[4][2];
        #pragma unroll
        for (int mi = 0; mi < 2; ++mi) {
            const uint16_t* pa = sA + (wm*32 + mi*16 + g4)*264 + kk;
            ah[mi][0] = *(const uint32_t*)pa;
            ah[mi][1] = *(const uint32_t*)(pa + 8*264);
            ah[mi][2] = *(const uint32_t*)(pa + 8);
            ah[mi][3] = *(const uint32_t*)(pa + 8*264 + 8);
        }
        #pragma unroll
        for (int ni = 0; ni < 4; ++ni) {
            const uint16_t* p = sW3 + (wn*32 + ni*8 + g4)*264 + kk;
            bb[ni][0] = *(const uint32_t*)p;
            bb[ni][1] = *(const uint32_t*)(p + 8);
        }
        #pragma unroll
        for (int mi = 0; mi < 2; ++mi)
            #pragma unroll
            for (int ni = 0; ni < 4; ++ni)
                mma_f16(acc[mi][ni], ah[mi], bb[ni]);
    }

    #pragma unroll
    for (int mi = 0; mi < 2; ++mi) {
        int m = wm*32 + mi*16 + g4;
        float c0 = scnt[m], c1 = scnt[m + 8];
        #pragma unroll
        for (int ni = 0; ni < 4; ++ni) {
            int n0 = wn*32 + ni*8 + l4*2;
            float b0 = sb3[n0], bv1 = sb3[n0 + 1];
            *(float2*)(out + (size_t)(m0 + m)*COUT + n0) =
                make_float2(acc[mi][ni][0] + b0*c0, acc[mi][ni][1] + bv1*c0);
            *(float2*)(out + (size_t)(m0 + m + 8)*COUT + n0) =
                make_float2(acc[mi][ni][2] + b0*c1, acc[mi][ni][3] + bv1*c1);
        }
    }
}

// ---------------------------------------------------------------------------
extern "C" void kernel_launch(void* const* d_in, const int* in_sizes, int n_in,
                              void* d_out, int out_size)
{
    const float* feats  = (const float*)d_in[2];
    const int*   n_idxs = (const int*)  d_in[3];
    const int*   nvalid = (const int*)  d_in[4];
    const float* W1     = (const float*)d_in[5];
    const float* b1     = (const float*)d_in[6];
    const float* W2     = (const float*)d_in[7];
    const float* b2     = (const float*)d_in[8];
    const float* W3     = (const float*)d_in[9];
    const float* b3     = (const float*)d_in[10];
    float* out = (float*)d_out;

    cudaFuncSetAttribute(k1_hmma, cudaFuncAttributeMaxDynamicSharedMemorySize, SMEM1);
    cudaFuncSetAttribute(k2_edge, cudaFuncAttributeMaxDynamicSharedMemorySize, SMEM2);
    cudaFuncSetAttribute(k3_hmma, cudaFuncAttributeMaxDynamicSharedMemorySize, SMEM3);

    k0_prep<<<668, 256>>>(W1, W2, W3);
    k1_hmma<<<dim3(128, 2), 256, SMEM1>>>(feats, b1);
    k2_edge<<<NODES/8, 256, SMEM2>>>(n_idxs, nvalid, b2);
    k3_hmma<<<256, 256, SMEM3>>>(nvalid, b3, out);
}

// round 17
// speedup vs baseline: 1.3410x; 1.2707x over previous
#include <cuda_runtime.h>
#include <cuda_bf16.h>
#include <cuda_fp16.h>
#include <cstdint>

#define B_    4
#define N_    4096
#define K_    16
#define CIN   128
#define H     256
#define COUT  128
#define NODES (B_*N_)
#define NTILE 2048

__device__ __align__(16) uint16_t g_Ah[NODES*H];  // fp16: feats@W1[:128,:] + b1
__device__ __align__(16) uint16_t g_Bh[NODES*H];  // fp16: feats@W1[128:,:]
__device__ float g_S [NODES*H];                   // fp32: sum_k mask*h2
// W1 packed fp16: [hf:2][n:256][k:136]
__device__ __align__(16) uint16_t g_W1h[2*256*136];
// W2 packed fp16 (FULL, n-major): [n:256][k:264]
__device__ __align__(16) uint16_t g_W2f[256*264];
// W3 packed fp16: [n:128][k:264]
__device__ __align__(16) uint16_t g_W3h[128*264];

// ---------------- helpers ----------------
__device__ __forceinline__ uint32_t smem_u32(const void* p) {
    uint32_t a;
    asm("{ .reg .u64 t; cvta.to.shared.u64 t, %1; cvt.u32.u64 %0, t; }" : "=r"(a) : "l"(p));
    return a;
}
__device__ __forceinline__ void mma_f16(float* d, const uint32_t* a, const uint32_t* b) {
    asm volatile("mma.sync.aligned.m16n8k16.row.col.f32.f16.f16.f32 "
        "{%0,%1,%2,%3}, {%4,%5,%6,%7}, {%8,%9}, {%0,%1,%2,%3};"
        : "+f"(d[0]), "+f"(d[1]), "+f"(d[2]), "+f"(d[3])
        : "r"(a[0]), "r"(a[1]), "r"(a[2]), "r"(a[3]), "r"(b[0]), "r"(b[1]));
}
__device__ __forceinline__ void cp16(uint32_t sdst, const void* gsrc) {
    asm volatile("cp.async.cg.shared.global [%0], [%1], 16;" :: "r"(sdst), "l"(gsrc));
}
__device__ __forceinline__ uint32_t pack_h2(float x, float y) {
    __half2 p = __floats2half2_rn(x, y);
    return *reinterpret_cast<uint32_t*>(&p);
}
__device__ __forceinline__ uint32_t relu_add_h2(uint32_t a, uint32_t b) {
    __half2 ha = *reinterpret_cast<__half2*>(&a);
    __half2 hb = *reinterpret_cast<__half2*>(&b);
    __half2 z  = __floats2half2_rn(0.f, 0.f);
    __half2 r  = __hmax2(__hadd2(ha, hb), z);
    return *reinterpret_cast<uint32_t*>(&r);
}

// ---------------------------------------------------------------------------
// k0: pack W2 (fp16 full n-major), W1 (fp16), W3 (fp16 n-major). Bounds-clean.
// ---------------------------------------------------------------------------
__global__ void k0_prep(const float* __restrict__ W1, const float* __restrict__ W2,
                        const float* __restrict__ W3)
{
    int i = blockIdx.x * 256 + threadIdx.x;
    if (i < 67584) {                                   // W2: [n:256][k:264]
        int k = i % 264, n = i / 264;
        __half v = (k < 256) ? __float2half_rn(W2[k*256 + n]) : __half(0.f);
        g_W2f[i] = *reinterpret_cast<uint16_t*>(&v);
    } else if (i < 67584 + 69632) {                    // W1: [hf][n][136] fp16
        int j = i - 67584;
        int k = j % 136, n = (j / 136) % 256, hf = j / 34816;
        __half v = (k < 128) ? __float2half_rn(W1[(hf*128 + k)*256 + n]) : __half(0.f);
        g_W1h[j] = *reinterpret_cast<uint16_t*>(&v);
    } else if (i < 67584 + 69632 + 33792) {            // W3: [n:128][k:264] fp16
        int j = i - 137216;
        int k = j % 264, n = j / 264;
        __half v = (k < 256) ? __float2half_rn(W3[k*COUT + n]) : __half(0.f);
        g_W3h[j] = *reinterpret_cast<uint16_t*>(&v);
    }
}

// ---------------------------------------------------------------------------
// k1 (HMMA fp16 single-term, R12-proven): grid (128, 2)
// ---------------------------------------------------------------------------
#define OFF1_W  0          // fp16 [256][136] = 69632 B
#define OFF1_A  69632      // fp16 [128][136] = 34816 B
#define OFF1_B1 104448     // 256 floats
#define SMEM1   105472

__global__ __launch_bounds__(256, 1)
void k1_hmma(const float* __restrict__ feats, const float* __restrict__ b1)
{
    extern __shared__ char sm1[];
    uint16_t* sW  = (uint16_t*)(sm1 + OFF1_W);
    uint16_t* sA  = (uint16_t*)(sm1 + OFF1_A);
    float*    sb1 = (float*)(sm1 + OFF1_B1);
    uint32_t  swb = smem_u32(sm1);

    int tid = threadIdx.x, lane = tid & 31, wid = tid >> 5;
    int wm = wid >> 2, wn = wid & 3, g4 = lane >> 2, l4 = lane & 3;
    int m0 = blockIdx.x * 128, hf = blockIdx.y;

    {
        const char* src = (const char*)(g_W1h + hf*34816) + tid*16;
        uint32_t dst = swb + OFF1_W + tid*16;
        #pragma unroll
        for (int it = 0; it < 17; ++it) cp16(dst + it*4096, src + it*4096);
        asm volatile("cp.async.commit_group;" ::: "memory");
    }
    sb1[tid] = (hf == 0) ? b1[tid] : 0.f;

    {
        int r = tid >> 1, kb = (tid & 1) * 64;
        const float* fr = feats + (size_t)(m0 + r)*CIN + kb;
        uint16_t* ph = sA + r*136 + kb;
        #pragma unroll
        for (int j = 0; j < 16; ++j) {
            float4 v = *(const float4*)(fr + 4*j);
            *(uint32_t*)(ph + 4*j)     = pack_h2(v.x, v.y);
            *(uint32_t*)(ph + 4*j + 2) = pack_h2(v.z, v.w);
        }
    }
    asm volatile("cp.async.wait_group 0;" ::: "memory");
    __syncthreads();

    float acc[4][8][4];
    #pragma unroll
    for (int mi = 0; mi < 4; ++mi)
        #pragma unroll
        for (int ni = 0; ni < 8; ++ni)
            #pragma unroll
            for (int q = 0; q < 4; ++q) acc[mi][ni][q] = 0.f;

    #pragma unroll
    for (int ks = 0; ks < 8; ++ks) {
        int kk = ks*16 + l4*2;
        uint32_t ah[4][4], bb[8][2];
        #pragma unroll
        for (int mi = 0; mi < 4; ++mi) {
            const uint16_t* pa = sA + (wm*64 + mi*16 + g4)*136 + kk;
            ah[mi][0] = *(const uint32_t*)pa;
            ah[mi][1] = *(const uint32_t*)(pa + 8*136);
            ah[mi][2] = *(const uint32_t*)(pa + 8);
            ah[mi][3] = *(const uint32_t*)(pa + 8*136 + 8);
        }
        #pragma unroll
        for (int ni = 0; ni < 8; ++ni) {
            const uint16_t* p = sW + (wn*64 + ni*8 + g4)*136 + kk;
            bb[ni][0] = *(const uint32_t*)p;
            bb[ni][1] = *(const uint32_t*)(p + 8);
        }
        #pragma unroll
        for (int mi = 0; mi < 4; ++mi)
            #pragma unroll
            for (int ni = 0; ni < 8; ++ni)
                mma_f16(acc[mi][ni], ah[mi], bb[ni]);
    }

    uint16_t* Out = hf ? g_Bh : g_Ah;
    #pragma unroll
    for (int mi = 0; mi < 4; ++mi) {
        int m = wm*64 + mi*16 + g4;
        #pragma unroll
        for (int ni = 0; ni < 8; ++ni) {
            int n0 = wn*64 + ni*8 + l4*2;
            float b0 = sb1[n0], bv1 = sb1[n0 + 1];
            *(uint32_t*)(Out + (size_t)(m0 + m)*H + n0) =
                pack_h2(acc[mi][ni][0] + b0, acc[mi][ni][1] + bv1);
            *(uint32_t*)(Out + (size_t)(m0 + m + 8)*H + n0) =
                pack_h2(acc[mi][ni][2] + b0, acc[mi][ni][3] + bv1);
        }
    }
}

// ---------------------------------------------------------------------------
// k2 PERSISTENT: grid=148, W2 streamed ONCE per CTA, loop over tiles.
// Per tile: warp-local idx (shfl), coalesced gather, 512 mma, epilogue.
// ---------------------------------------------------------------------------
#define OFF_H1   0          // fp16 [128][264] = 67584
#define OFF_W2   67584      // fp16 [256][264] = 135168 -> 202752
#define OFF_B2   202752
#define OFF_SVAL 203776     // 128 f
#define SMEM2    204800

__global__ __launch_bounds__(256, 1)
void k2_edge(const int* __restrict__ n_idxs, const int* __restrict__ nvalid,
             const float* __restrict__ b2, int ntiles)
{
    extern __shared__ char smem[];
    uint16_t* sh1  = (uint16_t*)(smem + OFF_H1);
    uint16_t* sW2  = (uint16_t*)(smem + OFF_W2);
    float*    sb2  = (float*)(smem + OFF_B2);
    float*    sval = (float*)(smem + OFF_SVAL);
    uint32_t  swb  = smem_u32(smem) + OFF_W2;

    int tid = threadIdx.x, lane = tid & 31, wid = tid >> 5;
    int wm = wid >> 2, wn = wid & 3;
    int g4 = lane >> 2, l4 = lane & 3;

    // stream FULL W2 once: 135168 B = 33 x 16B/thread
    {
        const char* src = (const char*)g_W2f + tid*16;
        uint32_t dst = swb + tid*16;
        #pragma unroll
        for (int it = 0; it < 33; ++it) cp16(dst + it*4096, src + it*4096);
        asm volatile("cp.async.commit_group;" ::: "memory");
    }
    sb2[tid] = b2[tid];
    asm volatile("cp.async.wait_group 0;" ::: "memory");
    __syncthreads();

    for (int tile = blockIdx.x; tile < ntiles; tile += gridDim.x) {
        int node0 = tile * 8;
        int node = node0 + wid;

        // warp-local neighbor idx/valid (lane<16), distribute via shfl
        int idxv = 0;
        if (lane < 16) {
            idxv = n_idxs[node*K_ + lane];
            sval[wid*16 + lane] = nvalid[node*K_ + lane] ? 1.f : 0.f;
        }

        // build h1 (fp16): warp owns node; 16 edges, 1 LDG.128/edge
        {
            int boff = (node >> 12) * N_;
            const uint16_t* arow = g_Ah + (size_t)node * H;
            uint4 a = *(const uint4*)(arow + 8*lane);
            #pragma unroll 4
            for (int i = 0; i < 16; ++i) {
                int gidx = __shfl_sync(0xFFFFFFFF, idxv, i);
                const uint16_t* brow = g_Bh + (size_t)(boff + gidx) * H;
                uint4 v = *(const uint4*)(brow + 8*lane);
                uint4 h;
                h.x = relu_add_h2(a.x, v.x);
                h.y = relu_add_h2(a.y, v.y);
                h.z = relu_add_h2(a.z, v.z);
                h.w = relu_add_h2(a.w, v.w);
                *(uint4*)(sh1 + (wid*16 + i)*264 + 8*lane) = h;
            }
        }
        __syncthreads();   // build done -> mainloop may read sh1/sval

        float acc[4][8][4];
        #pragma unroll
        for (int mi = 0; mi < 4; ++mi)
            #pragma unroll
            for (int ni = 0; ni < 8; ++ni)
                #pragma unroll
                for (int q = 0; q < 4; ++q) acc[mi][ni][q] = 0.f;

        // mainloop: 16 k-steps, no syncs
        #pragma unroll 4
        for (int ks = 0; ks < 16; ++ks) {
            int kk = ks*16 + l4*2;
            uint32_t ah[4][4], bb[8][2];
            #pragma unroll
            for (int mi = 0; mi < 4; ++mi) {
                const uint16_t* pa = sh1 + (wm*64 + mi*16 + g4)*264 + kk;
                ah[mi][0] = *(const uint32_t*)pa;
                ah[mi][1] = *(const uint32_t*)(pa + 8*264);
                ah[mi][2] = *(const uint32_t*)(pa + 8);
                ah[mi][3] = *(const uint32_t*)(pa + 8*264 + 8);
            }
            #pragma unroll
            for (int ni = 0; ni < 8; ++ni) {
                const uint16_t* p = sW2 + (wn*64 + ni*8 + g4)*264 + kk;
                bb[ni][0] = *(const uint32_t*)p;
                bb[ni][1] = *(const uint32_t*)(p + 8);
            }
            #pragma unroll
            for (int mi = 0; mi < 4; ++mi)
                #pragma unroll
                for (int ni = 0; ni < 8; ++ni)
                    mma_f16(acc[mi][ni], ah[mi], bb[ni]);
        }

        // epilogue: bias + relu + mask, butterfly over 16 edges, store g_S
        #pragma unroll
        for (int mi = 0; mi < 4; ++mi) {
            int node_l = wm*4 + mi;
            float m1 = sval[node_l*16 + g4];
            float m2 = sval[node_l*16 + g4 + 8];
            int node_g = node0 + node_l;
            #pragma unroll
            for (int ni = 0; ni < 8; ++ni) {
                int n0 = wn*64 + ni*8 + l4*2;
                float s0 = fmaxf(acc[mi][ni][0] + sb2[n0],     0.f)*m1
                         + fmaxf(acc[mi][ni][2] + sb2[n0],     0.f)*m2;
                float s1 = fmaxf(acc[mi][ni][1] + sb2[n0 + 1], 0.f)*m1
                         + fmaxf(acc[mi][ni][3] + sb2[n0 + 1], 0.f)*m2;
                #pragma unroll
                for (int d = 4; d < 32; d <<= 1) {
                    s0 += __shfl_xor_sync(0xFFFFFFFF, s0, d);
                    s1 += __shfl_xor_sync(0xFFFFFFFF, s1, d);
                }
                if (g4 == 0)
                    *(float2*)(g_S + (size_t)node_g*H + n0) = make_float2(s0, s1);
            }
        }
        __syncthreads();   // all mainloop/epilogue reads done -> next build may overwrite
    }
}

// ---------------------------------------------------------------------------
// k3 (R15-proven): fp16 single-term, BM=64, grid 256, 2 CTAs/SM
// ---------------------------------------------------------------------------
#define G3_A   0          // fp16 [64][264] = 33792
#define G3_W   33792      // fp16 [128][264] = 67584 -> 101376
#define G3_B3  101376
#define G3_CNT 101888
#define SMEM3  102400

__global__ __launch_bounds__(256, 2)
void k3_hmma(const int* __restrict__ nvalid, const float* __restrict__ b3,
             float* __restrict__ out)
{
    extern __shared__ char sm3[];
    uint16_t* sA   = (uint16_t*)(sm3 + G3_A);
    uint16_t* sW3  = (uint16_t*)(sm3 + G3_W);
    float*    sb3  = (float*)(sm3 + G3_B3);
    float*    scnt = (float*)(sm3 + G3_CNT);
    uint32_t  swb  = smem_u32(sm3);

    int tid = threadIdx.x, lane = tid & 31, wid = tid >> 5;
    int wm = wid >> 2, wn = wid & 3, g4 = lane >> 2, l4 = lane & 3;
    int m0 = blockIdx.x * 64;

    {
        const char* src = (const char*)g_W3h + tid*16;
        uint32_t dst = swb + G3_W + tid*16;
        #pragma unroll
        for (int it = 0; it < 17; ++it)
            if (it*4096 + tid*16 < 67584) cp16(dst + it*4096, src + it*4096);
        asm volatile("cp.async.commit_group;" ::: "memory");
    }
    if (tid < 128) sb3[tid] = b3[tid];
    if (tid < 64) {
        int c = 0;
        #pragma unroll
        for (int k = 0; k < K_; ++k) c += nvalid[(m0 + tid)*K_ + k];
        scnt[tid] = (float)c;
    }

    {
        int r = tid >> 2, kb = (tid & 3) * 64;
        const float* fr = g_S + (size_t)(m0 + r)*H + kb;
        uint16_t* ph = sA + r*264 + kb;
        #pragma unroll
        for (int j = 0; j < 16; ++j) {
            float4 v = *(const float4*)(fr + 4*j);
            *(uint32_t*)(ph + 4*j)     = pack_h2(v.x, v.y);
            *(uint32_t*)(ph + 4*j + 2) = pack_h2(v.z, v.w);
        }
    }
    asm volatile("cp.async.wait_group 0;" ::: "memory");
    __syncthreads();

    float acc[2][4][4];
    #pragma unroll
    for (int mi = 0; mi < 2; ++mi)
        #pragma unroll
        for (int ni = 0; ni < 4; ++ni)
            #pragma unroll
            for (int q = 0; q < 4; ++q) acc[mi][ni][q] = 0.f;

    #pragma unroll
    for (int ks = 0; ks < 16; ++ks) {
        int kk = ks*16 + l4*2;
        uint32_t ah[2][4], bb[4][2];
        #pragma unroll
        for (int mi = 0; mi < 2; ++mi) {
            const uint16_t* pa = sA + (wm*32 + mi*16 + g4)*264 + kk;
            ah[mi][0] = *(const uint32_t*)pa;
            ah[mi][1] = *(const uint32_t*)(pa + 8*264);
            ah[mi][2] = *(const uint32_t*)(pa + 8);
            ah[mi][3] = *(const uint32_t*)(pa + 8*264 + 8);
        }
        #pragma unroll
        for (int ni = 0; ni < 4; ++ni) {
            const uint16_t* p = sW3 + (wn*32 + ni*8 + g4)*264 + kk;
            bb[ni][0] = *(const uint32_t*)p;
            bb[ni][1] = *(const uint32_t*)(p + 8);
        }
        #pragma unroll
        for (int mi = 0; mi < 2; ++mi)
            #pragma unroll
            for (int ni = 0; ni < 4; ++ni)
                mma_f16(acc[mi][ni], ah[mi], bb[ni]);
    }

    #pragma unroll
    for (int mi = 0; mi < 2; ++mi) {
        int m = wm*32 + mi*16 + g4;
        float c0 = scnt[m], c1 = scnt[m + 8];
        #pragma unroll
        for (int ni = 0; ni < 4; ++ni) {
            int n0 = wn*32 + ni*8 + l4*2;
            float b0 = sb3[n0], bv1 = sb3[n0 + 1];
            *(float2*)(out + (size_t)(m0 + m)*COUT + n0) =
                make_float2(acc[mi][ni][0] + b0*c0, acc[mi][ni][1] + bv1*c0);
            *(float2*)(out + (size_t)(m0 + m + 8)*COUT + n0) =
                make_float2(acc[mi][ni][2] + b0*c1, acc[mi][ni][3] + bv1*c1);
        }
    }
}

// ---------------------------------------------------------------------------
extern "C" void kernel_launch(void* const* d_in, const int* in_sizes, int n_in,
                              void* d_out, int out_size)
{
    const float* feats  = (const float*)d_in[2];
    const int*   n_idxs = (const int*)  d_in[3];
    const int*   nvalid = (const int*)  d_in[4];
    const float* W1     = (const float*)d_in[5];
    const float* b1     = (const float*)d_in[6];
    const float* W2     = (const float*)d_in[7];
    const float* b2     = (const float*)d_in[8];
    const float* W3     = (const float*)d_in[9];
    const float* b3     = (const float*)d_in[10];
    float* out = (float*)d_out;

    cudaFuncSetAttribute(k1_hmma, cudaFuncAttributeMaxDynamicSharedMemorySize, SMEM1);
    cudaFuncSetAttribute(k2_edge, cudaFuncAttributeMaxDynamicSharedMemorySize, SMEM2);
    cudaFuncSetAttribute(k3_hmma, cudaFuncAttributeMaxDynamicSharedMemorySize, SMEM3);

    k0_prep<<<668, 256>>>(W1, W2, W3);
    k1_hmma<<<dim3(128, 2), 256, SMEM1>>>(feats, b1);
    k2_edge<<<148, 256, SMEM2>>>(n_idxs, nvalid, b2, NTILE);
    k3_hmma<<<256, 256, SMEM3>>>(nvalid, b3, out);
}